// round 9
// baseline (speedup 1.0000x reference)
#include <cuda_runtime.h>
#include <cuda_bf16.h>
#include <cstdint>

#define Bb 4
#define Tt 2048
#define Ee 512
#define KBLK 64
#define NBLK 32
#define MROWS (Bb * Tt)        // 8192
#define COMB_W (2 * Ee)        // 1024
#define NQKV (3 * Ee)          // 1536
#define KSPL 4
#define ESPL 4

// ---------------- scratch (__device__ globals) ------------------------------
__device__ float g_KQV[MROWS * NQKV];
__device__ __nv_bfloat16 g_xhi[MROWS * Ee];
__device__ __nv_bfloat16 g_xlo[MROWS * Ee];
__device__ __nv_bfloat16 g_Whi[NQKV * Ee];
__device__ __nv_bfloat16 g_Wlo[NQKV * Ee];
__device__ __nv_bfloat16 g_Uhi[Ee * COMB_W];
__device__ __nv_bfloat16 g_Ulo[Ee * COMB_W];
__device__ __nv_bfloat16 g_chi[MROWS * COMB_W];
__device__ __nv_bfloat16 g_clo[MROWS * COMB_W];
__device__ float g_bias[NQKV];
__device__ float g_S1part[KSPL * Bb * NBLK * 64 * 64];
__device__ float g_S2part[KSPL * Bb * NBLK * 64 * 32];

// ---------------- PTX helpers ----------------------------------------------
__device__ __forceinline__ uint32_t smem_u32(const void* p) {
    uint32_t a;
    asm("{ .reg .u64 t; cvta.to.shared.u64 t, %1; cvt.u32.u64 %0, t; }"
        : "=r"(a) : "l"(p));
    return a;
}
#define CP_ASYNC16(dst, src) \
    asm volatile("cp.async.cg.shared.global [%0], [%1], 16;" :: "r"(dst), "l"(src))
#define CP_COMMIT() asm volatile("cp.async.commit_group;" ::: "memory")
#define CP_WAITN(n) asm volatile("cp.async.wait_group %0;" :: "n"(n) : "memory")

__device__ __forceinline__ void ldm_x4(uint32_t* r, uint32_t addr) {
    asm volatile("ldmatrix.sync.aligned.m8n8.x4.shared.b16 {%0,%1,%2,%3}, [%4];"
                 : "=r"(r[0]), "=r"(r[1]), "=r"(r[2]), "=r"(r[3]) : "r"(addr));
}
__device__ __forceinline__ void mma16816(float* c, const uint32_t* a, const uint32_t* b) {
    asm volatile("mma.sync.aligned.m16n8k16.row.col.f32.bf16.bf16.f32 "
                 "{%0,%1,%2,%3}, {%4,%5,%6,%7}, {%8,%9}, {%0,%1,%2,%3};"
                 : "+f"(c[0]), "+f"(c[1]), "+f"(c[2]), "+f"(c[3])
                 : "r"(a[0]), "r"(a[1]), "r"(a[2]), "r"(a[3]), "r"(b[0]), "r"(b[1]));
}

// ---------------- split-bf16 NT GEMM: BK=16, 4-stage ring, 2 CTA/SM --------
#define ROWB 48                     // 16 cols bf16 = 32B data + 16B pad (bank-clean)
#define TILEB (128 * ROWB)          // 6144
#define STAGEB (4 * TILEB)          // 24576
#define NSTG 4
#define GM_SMEM (NSTG * STAGEB)     // 98304

__global__ __launch_bounds__(256, 2) void gemm_mma(
    const __nv_bfloat16* __restrict__ Ahi, const __nv_bfloat16* __restrict__ Alo,
    const __nv_bfloat16* __restrict__ Bhi, const __nv_bfloat16* __restrict__ Blo,
    const float* __restrict__ bias, float* __restrict__ C, int Kd, int Nout)
{
    extern __shared__ char smem[];
    const uint32_t sbase = smem_u32(smem);
    const int tid = threadIdx.x;
    const int wid = tid >> 5, lane = tid & 31;
    const int warp_m = wid & 3, warp_n = wid >> 2;
    const int m0 = blockIdx.y * 128, n0 = blockIdx.x * 128;

    // load mapping: each thread loads one 16B chunk per tile (4 tiles)
    const int row = tid >> 1;           // 0..127
    const int chk = tid & 1;            // 0/1 -> 16B halves
    const uint32_t dsto = (uint32_t)(row * ROWB + chk * 16);
    const int srco = chk * 8;           // element offset

    auto load_stage = [&](int s, int k0) {
        uint32_t dst = sbase + (uint32_t)(s & 3) * STAGEB;
        CP_ASYNC16(dst + dsto,             Ahi + (size_t)(m0 + row) * Kd + k0 + srco);
        CP_ASYNC16(dst + TILEB + dsto,     Alo + (size_t)(m0 + row) * Kd + k0 + srco);
        CP_ASYNC16(dst + 2 * TILEB + dsto, Bhi + (size_t)(n0 + row) * Kd + k0 + srco);
        CP_ASYNC16(dst + 3 * TILEB + dsto, Blo + (size_t)(n0 + row) * Kd + k0 + srco);
        CP_COMMIT();
    };

    float acc[2][8][4] = {};
    const int nstages = Kd >> 4;
    load_stage(0, 0);
    load_stage(1, 16);
    load_stage(2, 32);

    const uint32_t aRowOff = (uint32_t)(warp_m * 32 + (lane & 15)) * ROWB + ((lane >> 4) & 1) * 16;
    const int g = lane >> 3, lr = lane & 7;
    const uint32_t bRowOff = (uint32_t)(warp_n * 64 + ((g >> 1) & 1) * 8 + lr) * ROWB + (g & 1) * 16;

    for (int s = 0; s < nstages; s++) {
        // wait for stage s, single barrier per stage
        const int rem = nstages - 1 - s;
        if (rem >= 2) { CP_WAITN(2); }
        else if (rem == 1) { CP_WAITN(1); }
        else { CP_WAITN(0); }
        __syncthreads();
        if (s + 3 < nstages) load_stage(s + 3, (s + 3) << 4);

        const uint32_t st = sbase + (uint32_t)(s & 3) * STAGEB;
        const uint32_t sAh = st, sAl = st + TILEB, sBh = st + 2 * TILEB, sBl = st + 3 * TILEB;

        uint32_t ah[2][4], al[2][4];
#pragma unroll
        for (int mt = 0; mt < 2; mt++) {
            uint32_t ao = aRowOff + (uint32_t)mt * 16 * ROWB;
            ldm_x4(ah[mt], sAh + ao);
            ldm_x4(al[mt], sAl + ao);
        }
#pragma unroll
        for (int p = 0; p < 4; p++) {
            uint32_t bo = bRowOff + (uint32_t)p * 16 * ROWB;
            uint32_t bh[4], bl[4];
            ldm_x4(bh, sBh + bo);
            ldm_x4(bl, sBl + bo);
#pragma unroll
            for (int mt = 0; mt < 2; mt++)
#pragma unroll
                for (int j = 0; j < 2; j++) {
                    float* cc = acc[mt][2 * p + j];
                    mma16816(cc, ah[mt], &bh[j * 2]);
                    mma16816(cc, ah[mt], &bl[j * 2]);
                    mma16816(cc, al[mt], &bh[j * 2]);
                }
        }
    }

    const int mrow = m0 + warp_m * 32 + (lane >> 2);
    const int ncol0 = n0 + warp_n * 64 + (lane & 3) * 2;
#pragma unroll
    for (int mt = 0; mt < 2; mt++)
#pragma unroll
        for (int nt = 0; nt < 8; nt++) {
            int m = mrow + mt * 16;
            int n = ncol0 + nt * 8;
            float2 bv = *(const float2*)(bias + n);
            const float* cc = acc[mt][nt];
            float2 v0; v0.x = cc[0] + bv.x; v0.y = cc[1] + bv.y;
            float2 v1; v1.x = cc[2] + bv.x; v1.y = cc[3] + bv.y;
            *(float2*)(C + (size_t)m * Nout + n) = v0;
            *(float2*)(C + (size_t)(m + 8) * Nout + n) = v1;
        }
}

// ---------------- prep kernels (3 launches so QKV gemm is launch #4) --------
#define XN   (MROWS * Ee)
#define W3N  (3 * Ee * Ee)
#define WUN  (Ee * COMB_W)

__global__ void prep_x(const float* __restrict__ x)
{
    for (int i = blockIdx.x * blockDim.x + threadIdx.x; i < XN; i += gridDim.x * blockDim.x) {
        float v = x[i];
        __nv_bfloat16 h = __float2bfloat16(v);
        g_xhi[i] = h;
        g_xlo[i] = __float2bfloat16(v - __bfloat162float(h));
    }
}
__global__ void prep_w(const float* __restrict__ Wk, const float* __restrict__ Wq,
                       const float* __restrict__ Wv, const float* __restrict__ Wu)
{
    for (int i = blockIdx.x * blockDim.x + threadIdx.x; i < W3N + WUN; i += gridDim.x * blockDim.x) {
        if (i < W3N) {
            int wsel = i >> 18;
            int off = i & 262143;
            const float* W = (wsel == 0) ? Wk : (wsel == 1) ? Wq : Wv;
            float v = W[off];
            __nv_bfloat16 h = __float2bfloat16(v);
            g_Whi[i] = h;
            g_Wlo[i] = __float2bfloat16(v - __bfloat162float(h));
        } else {
            int off = i - W3N;
            float v = Wu[off];
            __nv_bfloat16 h = __float2bfloat16(v);
            g_Uhi[off] = h;
            g_Ulo[off] = __float2bfloat16(v - __bfloat162float(h));
        }
    }
}
__global__ void prep_bias(const float* __restrict__ bk, const float* __restrict__ bq,
                          const float* __restrict__ bv)
{
    int i = blockIdx.x * blockDim.x + threadIdx.x;
    if (i < Ee) {
        g_bias[i] = bk[i];
        g_bias[Ee + i] = bq[i];
        g_bias[2 * Ee + i] = bv[i];
    }
}

// store 4 fp32 as split hi/lo bf16
__device__ __forceinline__ void store_split4(float* o, size_t off) {
    __nv_bfloat16 h[4], l[4];
#pragma unroll
    for (int j = 0; j < 4; j++) {
        h[j] = __float2bfloat16(o[j]);
        l[j] = __float2bfloat16(o[j] - __bfloat162float(h[j]));
    }
    *(uint2*)(g_chi + off) = *(uint2*)h;
    *(uint2*)(g_clo + off) = *(uint2*)l;
}

// ---------------- merged scores (k-split): S1 and S2 from one K tile -------
__global__ __launch_bounds__(256) void hs_score()
{
    const int blk = blockIdx.x, b = blockIdx.y, ks = blockIdx.z;
    const int tid = threadIdx.x;
    const int ty = tid >> 4, tx = tid & 15;
    const int lr = tid >> 2, lk = (tid & 3) * 4;
    const size_t rbase = (size_t)b * Tt + (size_t)blk * KBLK;
    const int e0beg = ks * (Ee / KSPL);

    __shared__ float Ks[16][68];
    __shared__ float Qs[16][68];
    __shared__ float Q2[16][36];

    float acc1[4][4] = {};
    float acc2[4][2] = {};
    for (int e0 = e0beg; e0 < e0beg + Ee / KSPL; e0 += 16) {
        const float* rp = g_KQV + (rbase + lr) * NQKV;
        float4 vk = *(const float4*)(rp + e0 + lk);
        float4 vq = *(const float4*)(rp + Ee + e0 + lk);
        Ks[lk + 0][lr] = vk.x; Ks[lk + 1][lr] = vk.y;
        Ks[lk + 2][lr] = vk.z; Ks[lk + 3][lr] = vk.w;
        Qs[lk + 0][lr] = vq.x; Qs[lk + 1][lr] = vq.y;
        Qs[lk + 2][lr] = vq.z; Qs[lk + 3][lr] = vq.w;
        if (tid < 128) {
            int qi = tid >> 2;
            float4 v2 = *(const float4*)(g_KQV +
                ((size_t)b * Tt + (size_t)qi * KBLK) * NQKV + Ee + e0 + lk);
            Q2[lk + 0][qi] = v2.x; Q2[lk + 1][qi] = v2.y;
            Q2[lk + 2][qi] = v2.z; Q2[lk + 3][qi] = v2.w;
        }
        __syncthreads();
#pragma unroll
        for (int kk = 0; kk < 16; kk++) {
            float4 ra = *(const float4*)&Ks[kk][ty * 4];
            float4 rb = *(const float4*)&Qs[kk][tx * 4];
            float a_[4] = {ra.x, ra.y, ra.z, ra.w};
            float b_[4] = {rb.x, rb.y, rb.z, rb.w};
            float q0 = Q2[kk][tx * 2 + 0];
            float q1 = Q2[kk][tx * 2 + 1];
#pragma unroll
            for (int i = 0; i < 4; i++) {
#pragma unroll
                for (int j = 0; j < 4; j++)
                    acc1[i][j] += a_[i] * b_[j];
                acc2[i][0] += a_[i] * q0;
                acc2[i][1] += a_[i] * q1;
            }
        }
        __syncthreads();
    }
    float* d1 = g_S1part + (((size_t)ks * Bb + b) * NBLK + blk) * 4096;
    float* d2 = g_S2part + (((size_t)ks * Bb + b) * NBLK + blk) * 2048;
#pragma unroll
    for (int i = 0; i < 4; i++) {
        int r = ty * 4 + i;
        *(float4*)(d1 + r * 64 + tx * 4) = *(float4*)acc1[i];
        *(float2*)(d2 + r * 32 + tx * 2) = *(float2*)acc2[i];
    }
}

// ---------------- head1: output (e-split) -----------------------------------
__global__ __launch_bounds__(256) void h1_out()
{
    const int blk = blockIdx.x, b = blockIdx.y, ec = blockIdx.z;
    const int tid = threadIdx.x;
    const int ty = tid >> 4, tx = tid & 15;
    const size_t rbase = (size_t)b * Tt + (size_t)blk * KBLK;

    __shared__ float Ssh[64][68];
    __shared__ float Vs[64][68];

    const float* sp = g_S1part + (((size_t)b) * NBLK + blk) * 4096;
    const size_t kstride = (size_t)Bb * NBLK * 4096;
    for (int idx = tid; idx < 4096; idx += 256) {
        int r = idx >> 6, c = idx & 63;
        float s = sp[idx] + sp[idx + kstride] + sp[idx + 2 * kstride] + sp[idx + 3 * kstride];
        Ssh[c][r] = (c <= r) ? s : 0.0f;
    }
    __syncthreads();

    const int ebeg = ec * (Ee / ESPL);
    for (int e0 = ebeg; e0 < ebeg + Ee / ESPL; e0 += 64) {
#pragma unroll
        for (int l = 0; l < 4; l++) {
            int c = ty + l * 16;
            *(float4*)&Vs[c][tx * 4] =
                *(const float4*)(g_KQV + (rbase + c) * NQKV + 2 * Ee + e0 + tx * 4);
        }
        __syncthreads();
        float o[4][4] = {};
#pragma unroll 8
        for (int c = 0; c < 64; c++) {
            float4 rs = *(const float4*)&Ssh[c][ty * 4];
            float4 rv = *(const float4*)&Vs[c][tx * 4];
            float s_[4] = {rs.x, rs.y, rs.z, rs.w};
            float v_[4] = {rv.x, rv.y, rv.z, rv.w};
#pragma unroll
            for (int i = 0; i < 4; i++)
#pragma unroll
                for (int j = 0; j < 4; j++)
                    o[i][j] += s_[i] * v_[j];
        }
#pragma unroll
        for (int i = 0; i < 4; i++) {
            size_t row = rbase + ty * 4 + i;
            store_split4(o[i], row * COMB_W + e0 + tx * 4);
        }
        __syncthreads();
    }
}

// ---------------- head2: output (e-split) -----------------------------------
__global__ __launch_bounds__(256) void h2_out()
{
    const int rt = blockIdx.x, b = blockIdx.y, ec = blockIdx.z;
    const int tid = threadIdx.x;
    const int ty = tid >> 4, tx = tid & 15;
    const size_t rbase = (size_t)b * Tt + (size_t)rt * KBLK;

    __shared__ float S2[32][68];
    __shared__ float Vs[32][68];

    const float* sp = g_S2part + ((size_t)b * NBLK + rt) * 2048;
    const size_t kstride = (size_t)Bb * NBLK * 2048;
    for (int idx = tid; idx < 2048; idx += 256) {
        int r = idx >> 5, ii = idx & 31;
        float s = sp[idx] + sp[idx + kstride] + sp[idx + 2 * kstride] + sp[idx + 3 * kstride];
        S2[ii][r] = (ii <= rt) ? s : 0.0f;
    }
    __syncthreads();

    const int ebeg = ec * (Ee / ESPL);
    for (int e0 = ebeg; e0 < ebeg + Ee / ESPL; e0 += 64) {
#pragma unroll
        for (int l = 0; l < 2; l++) {
            int ii = (tid >> 4) + l * 16;
            *(float4*)&Vs[ii][(tid & 15) * 4] = *(const float4*)(g_KQV +
                ((size_t)b * Tt + (size_t)ii * KBLK) * NQKV + 2 * Ee + e0 + (tid & 15) * 4);
        }
        __syncthreads();
        float o[4][4] = {};
#pragma unroll 8
        for (int ii = 0; ii < 32; ii++) {
            float4 rs = *(const float4*)&S2[ii][ty * 4];
            float4 rv = *(const float4*)&Vs[ii][tx * 4];
            float s_[4] = {rs.x, rs.y, rs.z, rs.w};
            float v_[4] = {rv.x, rv.y, rv.z, rv.w};
#pragma unroll
            for (int i = 0; i < 4; i++)
#pragma unroll
                for (int j = 0; j < 4; j++)
                    o[i][j] += s_[i] * v_[j];
        }
#pragma unroll
        for (int i = 0; i < 4; i++) {
            size_t row = rbase + ty * 4 + i;
            store_split4(o[i], row * COMB_W + Ee + e0 + tx * 4);
        }
        __syncthreads();
    }
}

// ---------------------------------------------------------------------------
extern "C" void kernel_launch(void* const* d_in, const int* in_sizes, int n_in,
                              void* d_out, int out_size)
{
    const float* x  = (const float*)d_in[0];
    const float* Wk = (const float*)d_in[1];
    const float* bk = (const float*)d_in[2];
    const float* Wq = (const float*)d_in[3];
    const float* bq = (const float*)d_in[4];
    const float* Wv = (const float*)d_in[5];
    const float* bv = (const float*)d_in[6];
    const float* Wu = (const float*)d_in[7];
    const float* bu = (const float*)d_in[8];
    float* out = (float*)d_out;

    float *pKQV, *pBias;
    __nv_bfloat16 *pxh, *pxl, *pWh, *pWl, *pUh, *pUl, *pch, *pcl;
    cudaGetSymbolAddress((void**)&pKQV, g_KQV);
    cudaGetSymbolAddress((void**)&pBias, g_bias);
    cudaGetSymbolAddress((void**)&pxh, g_xhi);
    cudaGetSymbolAddress((void**)&pxl, g_xlo);
    cudaGetSymbolAddress((void**)&pWh, g_Whi);
    cudaGetSymbolAddress((void**)&pWl, g_Wlo);
    cudaGetSymbolAddress((void**)&pUh, g_Uhi);
    cudaGetSymbolAddress((void**)&pUl, g_Ulo);
    cudaGetSymbolAddress((void**)&pch, g_chi);
    cudaGetSymbolAddress((void**)&pcl, g_clo);

    cudaFuncSetAttribute(gemm_mma, cudaFuncAttributeMaxDynamicSharedMemorySize, GM_SMEM);

    // launches 1-3: prep
    prep_x<<<1024, 256>>>(x);
    prep_w<<<640, 256>>>(Wk, Wq, Wv, Wu);
    prep_bias<<<2, 256>>>(bk, bq, bv);

    // launch 4: fused QKV projection (profiled)
    gemm_mma<<<dim3(NQKV / 128, MROWS / 128), 256, GM_SMEM>>>(
        pxh, pxl, pWh, pWl, pBias, pKQV, Ee, NQKV);

    // launch 5: merged scores
    hs_score<<<dim3(NBLK, Bb, KSPL), 256>>>();

    // launches 6-7: head outputs
    h1_out<<<dim3(NBLK, Bb, ESPL), 256>>>();
    h2_out<<<dim3(NBLK, Bb, ESPL), 256>>>();

    // launch 8: final projection
    gemm_mma<<<dim3(Ee / 128, MROWS / 128), 256, GM_SMEM>>>(
        pch, pcl, pUh, pUl, bu, out, COMB_W, Ee);
}

// round 10
// speedup vs baseline: 1.1325x; 1.1325x over previous
#include <cuda_runtime.h>
#include <cuda_bf16.h>
#include <cstdint>

#define Bb 4
#define Tt 2048
#define Ee 512
#define KBLK 64
#define NBLK 32
#define MROWS (Bb * Tt)        // 8192
#define COMB_W (2 * Ee)        // 1024
#define NQKV (3 * Ee)          // 1536
#define ESPL 4

// ---------------- scratch (__device__ globals) ------------------------------
__device__ __nv_bfloat16 g_xhi[MROWS * Ee];
__device__ __nv_bfloat16 g_xlo[MROWS * Ee];
__device__ __nv_bfloat16 g_Whi[NQKV * Ee];
__device__ __nv_bfloat16 g_Wlo[NQKV * Ee];
__device__ __nv_bfloat16 g_Uhi[Ee * COMB_W];
__device__ __nv_bfloat16 g_Ulo[Ee * COMB_W];
__device__ __nv_bfloat16 g_chi[MROWS * COMB_W];
__device__ __nv_bfloat16 g_clo[MROWS * COMB_W];
__device__ __nv_bfloat16 g_kqh[MROWS * 1024];      // K|Q bf16 hi (stride 1024)
__device__ __nv_bfloat16 g_kql[MROWS * 1024];      // K|Q bf16 lo
__device__ float g_V[MROWS * Ee];                  // V fp32 (stride 512)
__device__ float g_bias[NQKV];
__device__ float g_S1[Bb * NBLK * 64 * 64];        // 2 MB
__device__ float g_S2[Bb * NBLK * 64 * 32];        // 1 MB

// ---------------- PTX helpers ----------------------------------------------
__device__ __forceinline__ uint32_t smem_u32(const void* p) {
    uint32_t a;
    asm("{ .reg .u64 t; cvta.to.shared.u64 t, %1; cvt.u32.u64 %0, t; }"
        : "=r"(a) : "l"(p));
    return a;
}
#define CP_ASYNC16(dst, src) \
    asm volatile("cp.async.cg.shared.global [%0], [%1], 16;" :: "r"(dst), "l"(src))
#define CP_COMMIT() asm volatile("cp.async.commit_group;" ::: "memory")
#define CP_WAIT1()  asm volatile("cp.async.wait_group 1;" ::: "memory")
#define CP_WAIT0()  asm volatile("cp.async.wait_group 0;" ::: "memory")

__device__ __forceinline__ void ldm_x4(uint32_t* r, uint32_t addr) {
    asm volatile("ldmatrix.sync.aligned.m8n8.x4.shared.b16 {%0,%1,%2,%3}, [%4];"
                 : "=r"(r[0]), "=r"(r[1]), "=r"(r[2]), "=r"(r[3]) : "r"(addr));
}
__device__ __forceinline__ void mma16816(float* c, const uint32_t* a, const uint32_t* b) {
    asm volatile("mma.sync.aligned.m16n8k16.row.col.f32.bf16.bf16.f32 "
                 "{%0,%1,%2,%3}, {%4,%5,%6,%7}, {%8,%9}, {%0,%1,%2,%3};"
                 : "+f"(c[0]), "+f"(c[1]), "+f"(c[2]), "+f"(c[3])
                 : "r"(a[0]), "r"(a[1]), "r"(a[2]), "r"(a[3]), "r"(b[0]), "r"(b[1]));
}

__device__ __forceinline__ void split_pair_store(
    float x, float y, __nv_bfloat16* hi, __nv_bfloat16* lo, size_t off)
{
    __nv_bfloat16 h0 = __float2bfloat16(x);
    __nv_bfloat16 h1 = __float2bfloat16(y);
    __nv_bfloat16 l0 = __float2bfloat16(x - __bfloat162float(h0));
    __nv_bfloat16 l1 = __float2bfloat16(y - __bfloat162float(h1));
    __nv_bfloat162 hh; hh.x = h0; hh.y = h1;
    __nv_bfloat162 ll; ll.x = l0; ll.y = l1;
    *(__nv_bfloat162*)(hi + off) = hh;
    *(__nv_bfloat162*)(lo + off) = ll;
}

// ---------------- split-bf16 NT GEMM (R8 config: BK=32, 2-stage, 2 CTA/SM) -
// mode 0: C = acc + bias (fp32)
// mode 1: QKV epilogue — n<1024: split bf16 -> g_kqh/g_kql ; n>=1024: fp32 -> g_V
#define ROWB 80
#define TILEB (128 * ROWB)
#define STAGEB (4 * TILEB)          // 40960
#define GM_SMEM (2 * STAGEB)        // 81920

__global__ __launch_bounds__(256, 2) void gemm_mma(
    const __nv_bfloat16* __restrict__ Ahi, const __nv_bfloat16* __restrict__ Alo,
    const __nv_bfloat16* __restrict__ Bhi, const __nv_bfloat16* __restrict__ Blo,
    const float* __restrict__ bias, float* __restrict__ C, int Kd, int Nout, int mode)
{
    extern __shared__ char smem[];
    const uint32_t sbase = smem_u32(smem);
    const int tid = threadIdx.x;
    const int wid = tid >> 5, lane = tid & 31;
    const int warp_m = wid & 3, warp_n = wid >> 2;
    const int m0 = blockIdx.y * 128, n0 = blockIdx.x * 128;

    const int r0 = tid >> 2;
    const int r1 = r0 + 64;
    const int c0 = (tid & 3) * 16;
    const int ce = (tid & 3) * 8;

    auto load_stage = [&](int s, int k0) {
        uint32_t dst = sbase + (s & 1) * STAGEB;
        const __nv_bfloat16* srcs[4] = {
            Ahi + (size_t)(m0 + r0) * Kd + k0 + ce,
            Alo + (size_t)(m0 + r0) * Kd + k0 + ce,
            Bhi + (size_t)(n0 + r0) * Kd + k0 + ce,
            Blo + (size_t)(n0 + r0) * Kd + k0 + ce };
#pragma unroll
        for (int t = 0; t < 4; t++) {
            uint32_t d = dst + t * TILEB;
            CP_ASYNC16(d + r0 * ROWB + c0, srcs[t]);
            CP_ASYNC16(d + r1 * ROWB + c0, srcs[t] + (size_t)64 * Kd);
        }
        CP_COMMIT();
    };

    float acc[2][8][4] = {};
    const int nstages = Kd >> 5;
    load_stage(0, 0);

    for (int s = 0; s < nstages; s++) {
        if (s + 1 < nstages) { load_stage(s + 1, (s + 1) << 5); CP_WAIT1(); }
        else                 { CP_WAIT0(); }
        __syncthreads();

        const uint32_t st = sbase + (s & 1) * STAGEB;
        const uint32_t sAh = st, sAl = st + TILEB, sBh = st + 2 * TILEB, sBl = st + 3 * TILEB;

        const uint32_t aRow = (uint32_t)(warp_m * 32 + (lane & 15)) * ROWB + ((lane >> 4) & 1) * 16;
        const int g = lane >> 3, lr = lane & 7;
        const uint32_t bRowBase = (uint32_t)(warp_n * 64 + ((g >> 1) & 1) * 8 + lr) * ROWB + (g & 1) * 16;

#pragma unroll
        for (int ks = 0; ks < 2; ks++) {
            uint32_t ah[2][4], al[2][4];
#pragma unroll
            for (int mt = 0; mt < 2; mt++) {
                uint32_t ao = aRow + (uint32_t)mt * 16 * ROWB + ks * 32;
                ldm_x4(ah[mt], sAh + ao);
                ldm_x4(al[mt], sAl + ao);
            }
#pragma unroll
            for (int p = 0; p < 4; p++) {
                uint32_t bo = bRowBase + (uint32_t)p * 16 * ROWB + ks * 32;
                uint32_t bh[4], bl[4];
                ldm_x4(bh, sBh + bo);
                ldm_x4(bl, sBl + bo);
#pragma unroll
                for (int mt = 0; mt < 2; mt++)
#pragma unroll
                    for (int j = 0; j < 2; j++) {
                        float* cc = acc[mt][2 * p + j];
                        mma16816(cc, ah[mt], &bh[j * 2]);
                        mma16816(cc, ah[mt], &bl[j * 2]);
                        mma16816(cc, al[mt], &bh[j * 2]);
                    }
            }
        }
        __syncthreads();
    }

    const int mrow = m0 + warp_m * 32 + (lane >> 2);
    const int ncol0 = n0 + warp_n * 64 + (lane & 3) * 2;
#pragma unroll
    for (int mt = 0; mt < 2; mt++)
#pragma unroll
        for (int nt = 0; nt < 8; nt++) {
            int m = mrow + mt * 16;
            int n = ncol0 + nt * 8;
            float2 bv = *(const float2*)(bias + n);
            const float* cc = acc[mt][nt];
            float x0 = cc[0] + bv.x, y0 = cc[1] + bv.y;
            float x1 = cc[2] + bv.x, y1 = cc[3] + bv.y;
            if (mode == 0) {
                float2 v0; v0.x = x0; v0.y = y0;
                float2 v1; v1.x = x1; v1.y = y1;
                *(float2*)(C + (size_t)m * Nout + n) = v0;
                *(float2*)(C + (size_t)(m + 8) * Nout + n) = v1;
            } else {
                if (n < 1024) {
                    split_pair_store(x0, y0, g_kqh, g_kql, (size_t)m * 1024 + n);
                    split_pair_store(x1, y1, g_kqh, g_kql, (size_t)(m + 8) * 1024 + n);
                } else {
                    float2 v0; v0.x = x0; v0.y = y0;
                    float2 v1; v1.x = x1; v1.y = y1;
                    *(float2*)(g_V + (size_t)m * Ee + (n - 1024)) = v0;
                    *(float2*)(g_V + (size_t)(m + 8) * Ee + (n - 1024)) = v1;
                }
            }
        }
}

// ---------------- prep kernels ---------------------------------------------
#define XN   (MROWS * Ee)
#define W3N  (3 * Ee * Ee)
#define WUN  (Ee * COMB_W)

__global__ void prep_x(const float* __restrict__ x)
{
    for (int i = blockIdx.x * blockDim.x + threadIdx.x; i < XN; i += gridDim.x * blockDim.x) {
        float v = x[i];
        __nv_bfloat16 h = __float2bfloat16(v);
        g_xhi[i] = h;
        g_xlo[i] = __float2bfloat16(v - __bfloat162float(h));
    }
}
__global__ void prep_w(const float* __restrict__ Wk, const float* __restrict__ Wq,
                       const float* __restrict__ Wv, const float* __restrict__ Wu)
{
    for (int i = blockIdx.x * blockDim.x + threadIdx.x; i < W3N + WUN; i += gridDim.x * blockDim.x) {
        if (i < W3N) {
            int wsel = i >> 18;
            int off = i & 262143;
            const float* W = (wsel == 0) ? Wk : (wsel == 1) ? Wq : Wv;
            float v = W[off];
            __nv_bfloat16 h = __float2bfloat16(v);
            g_Whi[i] = h;
            g_Wlo[i] = __float2bfloat16(v - __bfloat162float(h));
        } else {
            int off = i - W3N;
            float v = Wu[off];
            __nv_bfloat16 h = __float2bfloat16(v);
            g_Uhi[off] = h;
            g_Ulo[off] = __float2bfloat16(v - __bfloat162float(h));
        }
    }
}
__global__ void prep_bias(const float* __restrict__ bk, const float* __restrict__ bq,
                          const float* __restrict__ bv)
{
    int i = blockIdx.x * blockDim.x + threadIdx.x;
    if (i < Ee) {
        g_bias[i] = bk[i];
        g_bias[Ee + i] = bq[i];
        g_bias[2 * Ee + i] = bv[i];
    }
}

// store 4 fp32 as split hi/lo bf16 (comb)
__device__ __forceinline__ void store_split4(float* o, size_t off) {
    __nv_bfloat16 h[4], l[4];
#pragma unroll
    for (int j = 0; j < 4; j++) {
        h[j] = __float2bfloat16(o[j]);
        l[j] = __float2bfloat16(o[j] - __bfloat162float(h[j]));
    }
    *(uint2*)(g_chi + off) = *(uint2*)h;
    *(uint2*)(g_clo + off) = *(uint2*)l;
}

// ---------------- tensorized merged scores ---------------------------------
// Per (blk, b): S[64 x 128] = K_blk(64xK512) . B^T where B rows =
//   [Q_blk (64) ; Q_starts (32) ; dup Q_starts (32, discarded)]
// cols 0..63 -> g_S1, 64..95 -> g_S2. 3-product split-bf16 mma.
#define HS_AROWS 64
#define HS_ATILE (HS_AROWS * ROWB)      // 5120
#define HS_BTILE (128 * ROWB)           // 10240
#define HS_STAGE (2 * HS_ATILE + 2 * HS_BTILE)   // 30720
#define HS_SMEM (2 * HS_STAGE)          // 61440

__global__ __launch_bounds__(256) void hs_score_mma()
{
    extern __shared__ char smem[];
    const uint32_t sbase = smem_u32(smem);
    const int blk = blockIdx.x, b = blockIdx.y;
    const int tid = threadIdx.x;
    const int wid = tid >> 5, lane = tid & 31;
    const int warp_m = wid & 3;          // 4 x 16 rows
    const int warp_n = wid >> 2;         // 2 x 64 cols
    const size_t rbase = (size_t)b * Tt + (size_t)blk * KBLK;

    auto load_stage = [&](int s, int k0) {
        uint32_t dst = sbase + (uint32_t)(s & 1) * HS_STAGE;
#pragma unroll
        for (int j = 0; j < 6; j++) {
            int f = tid + j * 256;                   // 0..1535
            if (f < 512) {                           // A = K rows (hi, lo)
                const __nv_bfloat16* base = (f < 256) ? g_kqh : g_kql;
                int r = (f >> 2) & 63, c = f & 3;
                CP_ASYNC16(dst + ((f < 256) ? 0u : (uint32_t)HS_ATILE) + r * ROWB + c * 16,
                           base + (rbase + r) * 1024 + k0 + c * 8);
            } else {                                 // B = gathered Q rows (hi, lo)
                int fb = f - 512;
                const __nv_bfloat16* base = (fb < 512) ? g_kqh : g_kql;
                int r = (fb >> 2) & 127, c = fb & 3;
                size_t tok = (size_t)b * Tt +
                    ((r < 64) ? (size_t)(blk * KBLK + r) : (size_t)((r & 31) * KBLK));
                CP_ASYNC16(dst + 2 * HS_ATILE + ((fb < 512) ? 0u : (uint32_t)HS_BTILE)
                               + r * ROWB + c * 16,
                           base + tok * 1024 + 512 + k0 + c * 8);
            }
        }
        CP_COMMIT();
    };

    float acc[8][4] = {};
    const int nstages = Ee >> 5;        // 16
    load_stage(0, 0);

    const uint32_t aRow = (uint32_t)(warp_m * 16 + (lane & 15)) * ROWB + ((lane >> 4) & 1) * 16;
    const int g = lane >> 3, lr = lane & 7;
    const uint32_t bRowBase = (uint32_t)(warp_n * 64 + ((g >> 1) & 1) * 8 + lr) * ROWB + (g & 1) * 16;

    for (int s = 0; s < nstages; s++) {
        if (s + 1 < nstages) { load_stage(s + 1, (s + 1) << 5); CP_WAIT1(); }
        else                 { CP_WAIT0(); }
        __syncthreads();

        const uint32_t st = sbase + (uint32_t)(s & 1) * HS_STAGE;
        const uint32_t sAh = st, sAl = st + HS_ATILE;
        const uint32_t sBh = st + 2 * HS_ATILE, sBl = sBh + HS_BTILE;

#pragma unroll
        for (int ks = 0; ks < 2; ks++) {
            uint32_t ah[4], al[4];
            uint32_t ao = aRow + ks * 32;
            ldm_x4(ah, sAh + ao);
            ldm_x4(al, sAl + ao);
#pragma unroll
            for (int p = 0; p < 4; p++) {
                uint32_t bo = bRowBase + (uint32_t)p * 16 * ROWB + ks * 32;
                uint32_t bh[4], bl[4];
                ldm_x4(bh, sBh + bo);
                ldm_x4(bl, sBl + bo);
#pragma unroll
                for (int j = 0; j < 2; j++) {
                    float* cc = acc[2 * p + j];
                    mma16816(cc, ah, &bh[j * 2]);
                    mma16816(cc, ah, &bl[j * 2]);
                    mma16816(cc, al, &bh[j * 2]);
                }
            }
        }
        __syncthreads();
    }

    float* d1 = g_S1 + ((size_t)b * NBLK + blk) * 4096;
    float* d2 = g_S2 + ((size_t)b * NBLK + blk) * 2048;
    const int rr = warp_m * 16 + (lane >> 2);
    const int cc0 = warp_n * 64 + (lane & 3) * 2;
#pragma unroll
    for (int nt = 0; nt < 8; nt++) {
        int c = cc0 + nt * 8;
        const float* cc = acc[nt];
        if (c < 64) {
            float2 v0; v0.x = cc[0]; v0.y = cc[1];
            float2 v1; v1.x = cc[2]; v1.y = cc[3];
            *(float2*)(d1 + rr * 64 + c) = v0;
            *(float2*)(d1 + (rr + 8) * 64 + c) = v1;
        } else if (c < 96) {
            float2 v0; v0.x = cc[0]; v0.y = cc[1];
            float2 v1; v1.x = cc[2]; v1.y = cc[3];
            *(float2*)(d2 + rr * 32 + (c - 64)) = v0;
            *(float2*)(d2 + (rr + 8) * 32 + (c - 64)) = v1;
        }
    }
}

// ---------------- head1: output (e-split) -----------------------------------
__global__ __launch_bounds__(256) void h1_out()
{
    const int blk = blockIdx.x, b = blockIdx.y, ec = blockIdx.z;
    const int tid = threadIdx.x;
    const int ty = tid >> 4, tx = tid & 15;
    const size_t rbase = (size_t)b * Tt + (size_t)blk * KBLK;

    __shared__ float Ssh[64][68];
    __shared__ float Vs[64][68];

    const float* sp = g_S1 + ((size_t)b * NBLK + blk) * 4096;
    for (int idx = tid; idx < 4096; idx += 256) {
        int r = idx >> 6, c = idx & 63;
        Ssh[c][r] = (c <= r) ? sp[idx] : 0.0f;
    }
    __syncthreads();

    const int ebeg = ec * (Ee / ESPL);
    for (int e0 = ebeg; e0 < ebeg + Ee / ESPL; e0 += 64) {
#pragma unroll
        for (int l = 0; l < 4; l++) {
            int c = ty + l * 16;
            *(float4*)&Vs[c][tx * 4] =
                *(const float4*)(g_V + (rbase + c) * Ee + e0 + tx * 4);
        }
        __syncthreads();
        float o[4][4] = {};
#pragma unroll 8
        for (int c = 0; c < 64; c++) {
            float4 rs = *(const float4*)&Ssh[c][ty * 4];
            float4 rv = *(const float4*)&Vs[c][tx * 4];
            float s_[4] = {rs.x, rs.y, rs.z, rs.w};
            float v_[4] = {rv.x, rv.y, rv.z, rv.w};
#pragma unroll
            for (int i = 0; i < 4; i++)
#pragma unroll
                for (int j = 0; j < 4; j++)
                    o[i][j] += s_[i] * v_[j];
        }
#pragma unroll
        for (int i = 0; i < 4; i++) {
            size_t row = rbase + ty * 4 + i;
            store_split4(o[i], row * COMB_W + e0 + tx * 4);
        }
        __syncthreads();
    }
}

// ---------------- head2: output (e-split) -----------------------------------
__global__ __launch_bounds__(256) void h2_out()
{
    const int rt = blockIdx.x, b = blockIdx.y, ec = blockIdx.z;
    const int tid = threadIdx.x;
    const int ty = tid >> 4, tx = tid & 15;
    const size_t rbase = (size_t)b * Tt + (size_t)rt * KBLK;

    __shared__ float S2[32][68];
    __shared__ float Vs[32][68];

    const float* sp = g_S2 + ((size_t)b * NBLK + rt) * 2048;
    for (int idx = tid; idx < 2048; idx += 256) {
        int r = idx >> 5, ii = idx & 31;
        S2[ii][r] = (ii <= rt) ? sp[idx] : 0.0f;
    }
    __syncthreads();

    const int ebeg = ec * (Ee / ESPL);
    for (int e0 = ebeg; e0 < ebeg + Ee / ESPL; e0 += 64) {
#pragma unroll
        for (int l = 0; l < 2; l++) {
            int ii = (tid >> 4) + l * 16;
            *(float4*)&Vs[ii][(tid & 15) * 4] = *(const float4*)(g_V +
                ((size_t)b * Tt + (size_t)ii * KBLK) * Ee + e0 + (tid & 15) * 4);
        }
        __syncthreads();
        float o[4][4] = {};
#pragma unroll 8
        for (int ii = 0; ii < 32; ii++) {
            float4 rs = *(const float4*)&S2[ii][ty * 4];
            float4 rv = *(const float4*)&Vs[ii][tx * 4];
            float s_[4] = {rs.x, rs.y, rs.z, rs.w};
            float v_[4] = {rv.x, rv.y, rv.z, rv.w};
#pragma unroll
            for (int i = 0; i < 4; i++)
#pragma unroll
                for (int j = 0; j < 4; j++)
                    o[i][j] += s_[i] * v_[j];
        }
#pragma unroll
        for (int i = 0; i < 4; i++) {
            size_t row = rbase + ty * 4 + i;
            store_split4(o[i], row * COMB_W + Ee + e0 + tx * 4);
        }
        __syncthreads();
    }
}

// ---------------------------------------------------------------------------
extern "C" void kernel_launch(void* const* d_in, const int* in_sizes, int n_in,
                              void* d_out, int out_size)
{
    const float* x  = (const float*)d_in[0];
    const float* Wk = (const float*)d_in[1];
    const float* bk = (const float*)d_in[2];
    const float* Wq = (const float*)d_in[3];
    const float* bq = (const float*)d_in[4];
    const float* Wv = (const float*)d_in[5];
    const float* bv = (const float*)d_in[6];
    const float* Wu = (const float*)d_in[7];
    const float* bu = (const float*)d_in[8];
    float* out = (float*)d_out;

    float *pBias;
    __nv_bfloat16 *pxh, *pxl, *pWh, *pWl, *pUh, *pUl, *pch, *pcl;
    cudaGetSymbolAddress((void**)&pBias, g_bias);
    cudaGetSymbolAddress((void**)&pxh, g_xhi);
    cudaGetSymbolAddress((void**)&pxl, g_xlo);
    cudaGetSymbolAddress((void**)&pWh, g_Whi);
    cudaGetSymbolAddress((void**)&pWl, g_Wlo);
    cudaGetSymbolAddress((void**)&pUh, g_Uhi);
    cudaGetSymbolAddress((void**)&pUl, g_Ulo);
    cudaGetSymbolAddress((void**)&pch, g_chi);
    cudaGetSymbolAddress((void**)&pcl, g_clo);

    cudaFuncSetAttribute(gemm_mma, cudaFuncAttributeMaxDynamicSharedMemorySize, GM_SMEM);
    cudaFuncSetAttribute(hs_score_mma, cudaFuncAttributeMaxDynamicSharedMemorySize, HS_SMEM);

    // launches 1-3: prep
    prep_x<<<1024, 256>>>(x);
    prep_w<<<640, 256>>>(Wk, Wq, Wv, Wu);
    prep_bias<<<2, 256>>>(bk, bq, bv);

    // launch 4: fused QKV projection -> split bf16 K|Q + fp32 V
    gemm_mma<<<dim3(NQKV / 128, MROWS / 128), 256, GM_SMEM>>>(
        pxh, pxl, pWh, pWl, pBias, nullptr, Ee, NQKV, 1);

    // launch 5: tensorized merged scores
    hs_score_mma<<<dim3(NBLK, Bb), 256, HS_SMEM>>>();

    // launches 6-7: head outputs
    h1_out<<<dim3(NBLK, Bb, ESPL), 256>>>();
    h2_out<<<dim3(NBLK, Bb, ESPL), 256>>>();

    // launch 8: final projection
    gemm_mma<<<dim3(Ee / 128, MROWS / 128), 256, GM_SMEM>>>(
        pch, pcl, pUh, pUl, bu, out, COMB_W, Ee, 0);
}